// round 7
// baseline (speedup 1.0000x reference)
#include <cuda_runtime.h>
#include <cstdint>

// x: [B=16, C=8, T=262144] fp32 row-major.
// out = x * (c == 0 ? 1.0f : 0.5f)
//
// Persistent single-wave grid: 592 blocks (148 SMs x 4 co-resident 512-thread
// blocks), grid-striding over 4096 contiguous 32 KB tiles. Removes all block
// wave transitions; next tile's 256-bit loads overlap prior tile's store drain.
//
// Units: float8 (32 B). Tile = 1024 vec8. Channel row = 32768 vec8 = 32 tiles,
// so channel is uniform per tile: channel = (tile >> 5) & 7.

static constexpr long long N_VEC8   = (16LL * 8LL * 262144LL) / 8;  // 4,194,304
static constexpr int       THREADS  = 512;
static constexpr int       UNROLL   = 2;
static constexpr int       TILE     = THREADS * UNROLL;             // 1024 vec8
static constexpr int       N_TILES  = (int)(N_VEC8 / TILE);         // 4096
static constexpr int       BLOCKS   = 148 * 4;                      // 592, single wave

struct alignas(32) f8 { float v[8]; };

__device__ __forceinline__ f8 ldg256(const f8* p) {
    f8 r;
    asm volatile(
        "ld.global.nc.v8.f32 {%0, %1, %2, %3, %4, %5, %6, %7}, [%8];"
        : "=f"(r.v[0]), "=f"(r.v[1]), "=f"(r.v[2]), "=f"(r.v[3]),
          "=f"(r.v[4]), "=f"(r.v[5]), "=f"(r.v[6]), "=f"(r.v[7])
        : "l"(p));
    return r;
}

__device__ __forceinline__ void stg256(f8* p, const f8& r) {
    asm volatile(
        "st.global.cs.v8.f32 [%0], {%1, %2, %3, %4, %5, %6, %7, %8};"
        :: "l"(p),
           "f"(r.v[0]), "f"(r.v[1]), "f"(r.v[2]), "f"(r.v[3]),
           "f"(r.v[4]), "f"(r.v[5]), "f"(r.v[6]), "f"(r.v[7])
        : "memory");
}

__global__ void __launch_bounds__(THREADS) channel_scale_kernel(
    const f8* __restrict__ x, f8* __restrict__ out)
{
    for (int tile = blockIdx.x; tile < N_TILES; tile += BLOCKS) {
        // Uniform channel per 32 KB tile: bits [5:8) of tile index.
        const float s = ((tile & (7 << 5)) == 0) ? 1.0f : 0.5f;

        const long long base = (long long)tile * TILE + threadIdx.x;

        f8 a[UNROLL];
#pragma unroll
        for (int k = 0; k < UNROLL; k++) {
            a[k] = ldg256(&x[base + k * THREADS]);
        }

#pragma unroll
        for (int k = 0; k < UNROLL; k++) {
#pragma unroll
            for (int j = 0; j < 8; j++) a[k].v[j] *= s;
            stg256(&out[base + k * THREADS], a[k]);
        }
    }
}

extern "C" void kernel_launch(void* const* d_in, const int* in_sizes, int n_in,
                              void* d_out, int out_size)
{
    const f8* x = (const f8*)d_in[0];
    f8* out = (f8*)d_out;
    channel_scale_kernel<<<BLOCKS, THREADS>>>(x, out);
}

// round 8
// speedup vs baseline: 1.1317x; 1.1317x over previous
#include <cuda_runtime.h>
#include <cstdint>

// x: [B=16, C=8, T=262144] fp32 row-major.
// out = x * (c == 0 ? 1.0f : 0.5f)
//
// Final kernel (best of 7 rounds): block-contiguous 32 KB tiles, 512 threads,
// Blackwell 256-bit global loads/stores, per-block uniform channel scale.
// Measured: 43.49 us bench / 35.58 us ncu, DRAM 75.3% = GB300 mixed-R/W
// streaming wall (persistent grids, deeper ILP, L2 policies all tested worse
// or neutral).
//
// Units: float8 (32 B). Channel row = T/8 = 32768 vec8 = 32 tiles of 1024,
// so channel is uniform per block: channel = (blockIdx.x >> 5) & 7.

static constexpr long long N_VEC8  = (16LL * 8LL * 262144LL) / 8;  // 4,194,304
static constexpr int       THREADS = 512;
static constexpr int       UNROLL  = 2;
static constexpr int       TILE    = THREADS * UNROLL;             // 1024 vec8 = 32 KB
static constexpr int       BLOCKS  = (int)(N_VEC8 / TILE);         // 4096, exact

struct alignas(32) f8 { float v[8]; };

__device__ __forceinline__ f8 ldg256(const f8* p) {
    f8 r;
    asm volatile(
        "ld.global.nc.v8.f32 {%0, %1, %2, %3, %4, %5, %6, %7}, [%8];"
        : "=f"(r.v[0]), "=f"(r.v[1]), "=f"(r.v[2]), "=f"(r.v[3]),
          "=f"(r.v[4]), "=f"(r.v[5]), "=f"(r.v[6]), "=f"(r.v[7])
        : "l"(p));
    return r;
}

__device__ __forceinline__ void stg256(f8* p, const f8& r) {
    asm volatile(
        "st.global.v8.f32 [%0], {%1, %2, %3, %4, %5, %6, %7, %8};"
        :: "l"(p),
           "f"(r.v[0]), "f"(r.v[1]), "f"(r.v[2]), "f"(r.v[3]),
           "f"(r.v[4]), "f"(r.v[5]), "f"(r.v[6]), "f"(r.v[7])
        : "memory");
}

__global__ void __launch_bounds__(THREADS) channel_scale_kernel(
    const f8* __restrict__ x, f8* __restrict__ out)
{
    // Per-block uniform channel scale: channel = (blockIdx.x >> 5) & 7.
    const float s = ((blockIdx.x & (7u << 5)) == 0u) ? 1.0f : 0.5f;

    const long long base = (long long)blockIdx.x * TILE + threadIdx.x;

    f8 a[UNROLL];
#pragma unroll
    for (int k = 0; k < UNROLL; k++) {
        a[k] = ldg256(&x[base + k * THREADS]);
    }

#pragma unroll
    for (int k = 0; k < UNROLL; k++) {
#pragma unroll
        for (int j = 0; j < 8; j++) a[k].v[j] *= s;
        stg256(&out[base + k * THREADS], a[k]);
    }
}

extern "C" void kernel_launch(void* const* d_in, const int* in_sizes, int n_in,
                              void* d_out, int out_size)
{
    const f8* x = (const f8*)d_in[0];
    f8* out = (f8*)d_out;
    channel_scale_kernel<<<BLOCKS, THREADS>>>(x, out);
}